// round 2
// baseline (speedup 1.0000x reference)
#include <cuda_runtime.h>
#include <math.h>

// Problem constants
constexpr int Nn  = 4096;    // nodes
constexpr int Ee  = 131072;  // edges
constexpr int Cin = 128;
constexpr int Hh  = 256;
constexpr int H3  = 768;     // 3H
constexpr int H4  = 1024;    // 4H
constexpr int Hd2 = 512;     // 2H
constexpr int NC  = 16;
constexpr int NH  = 4;
constexpr int HD  = 64;

// ---------------- scratch arena (single device global; no allocation) ----------------
// layout (floats):
constexpr size_t OFF_DEG    = 0;                        // 4096
constexpr size_t OFF_DINV   = OFF_DEG    + Nn;          // 4096
constexpr size_t OFF_H      = OFF_DINV   + Nn;          // Nn*Hh
constexpr size_t OFF_AGG    = OFF_H      + (size_t)Nn * Hh;
constexpr size_t OFF_XLOC   = OFF_AGG    + (size_t)Nn * Hh;
constexpr size_t OFF_QKV    = OFF_XLOC   + (size_t)Nn * Hh;
constexpr size_t OFF_CTX    = OFF_QKV    + (size_t)Nn * H3;
constexpr size_t OFF_ATTN   = OFF_CTX    + (size_t)Nn * Hh;
constexpr size_t OFF_Y      = OFF_ATTN   + (size_t)Nn * Hh;
constexpr size_t OFF_FFN    = OFF_Y      + (size_t)Nn * Hh;
constexpr size_t SCRATCH_FLOATS = OFF_FFN + (size_t)Nn * H4;

__device__ float g_scratch[SCRATCH_FLOATS];

// ---------------- small helpers ----------------
__device__ __forceinline__ void red_add_v4(float* p, float x, float y, float z, float w) {
    asm volatile("red.global.add.v4.f32 [%0], {%1,%2,%3,%4};"
                 :: "l"(p), "f"(x), "f"(y), "f"(z), "f"(w) : "memory");
}

// ---------------- degree / norm ----------------
__global__ void deg_init_kernel(float* deg) {
    int i = blockIdx.x * blockDim.x + threadIdx.x;
    if (i < Nn) deg[i] = 1.0f;  // self-loop weight
}

__global__ void deg_scatter_kernel(const int* __restrict__ ei,
                                   const float* __restrict__ ea, float* deg) {
    int e = blockIdx.x * blockDim.x + threadIdx.x;
    if (e < Ee) atomicAdd(&deg[ei[Ee + e]], ea[e]);
}

__global__ void dinv_kernel(const float* __restrict__ deg, float* dinv) {
    int i = blockIdx.x * blockDim.x + threadIdx.x;
    if (i < Nn) dinv[i] = rsqrtf(deg[i]);
}

// out[n][:] = dinv[n]^2 * h[n][:]   (self-loop term; also initializes accum buffer)
__global__ void selfloop_kernel(const float* __restrict__ h,
                                const float* __restrict__ dinv,
                                float* __restrict__ out) {
    int i = blockIdx.x * blockDim.x + threadIdx.x;  // over Nn*64 float4s
    if (i >= Nn * (Hh / 4)) return;
    int n = i / (Hh / 4);
    float s = dinv[n]; s *= s;
    float4 v = ((const float4*)h)[i];
    v.x *= s; v.y *= s; v.z *= s; v.w *= s;
    ((float4*)out)[i] = v;
}

// warp per edge: out[dst] += dinv[src]*ew*dinv[dst] * h[src]
__global__ void edge_scatter_kernel(const int* __restrict__ ei,
                                    const float* __restrict__ ea,
                                    const float* __restrict__ dinv,
                                    const float* __restrict__ h,
                                    float* __restrict__ out) {
    int t = blockIdx.x * blockDim.x + threadIdx.x;
    int e = t >> 5, lane = t & 31;
    if (e >= Ee) return;
    int s = ei[e], d = ei[Ee + e];
    float w = dinv[s] * ea[e] * dinv[d];
    const float4* hs = (const float4*)(h + (size_t)s * Hh);
    float* od = out + (size_t)d * Hh;
    #pragma unroll
    for (int q = 0; q < 2; ++q) {
        int idx = lane + q * 32;                 // float4 index, 64 per row
        float4 v = hs[idx];
        red_add_v4(od + idx * 4, v.x * w, v.y * w, v.z * w, v.w * w);
    }
}

// in-place: x = act(x + b[col]),  width Hh
__global__ void bias_act_kernel(float* __restrict__ x, const float* __restrict__ b, int relu) {
    int i = blockIdx.x * blockDim.x + threadIdx.x;  // over Nn*64 float4s
    if (i >= Nn * (Hh / 4)) return;
    int c = (i & (Hh / 4 - 1)) * 4;
    float4 v = ((float4*)x)[i];
    float4 bv = *(const float4*)&b[c];
    v.x += bv.x; v.y += bv.y; v.z += bv.z; v.w += bv.w;
    if (relu) { v.x = fmaxf(v.x, 0.f); v.y = fmaxf(v.y, 0.f); v.z = fmaxf(v.z, 0.f); v.w = fmaxf(v.w, 0.f); }
    ((float4*)x)[i] = v;
}

__global__ void add_kernel(const float* __restrict__ a, const float* __restrict__ b,
                           float* __restrict__ out) {
    int i = blockIdx.x * blockDim.x + threadIdx.x;
    if (i >= Nn * (Hh / 4)) return;
    float4 va = ((const float4*)a)[i], vb = ((const float4*)b)[i];
    va.x += vb.x; va.y += vb.y; va.z += vb.z; va.w += vb.w;
    ((float4*)out)[i] = va;
}

// ---------------- tiled GEMM: C = act(A @ B (+bias)) ----------------
// A [M,K] row-major. TRANSB=false: B [K,N] row-major. TRANSB=true: B [N,K] row-major (C = A @ B^T).
// 128x128 tile, BK=16, 256 threads, 8x8 per thread (split 4+4 halves).
template <bool TRANSB, bool RELU>
__global__ void __launch_bounds__(256) gemm_kernel(
    const float* __restrict__ A, const float* __restrict__ B,
    const float* __restrict__ bias, float* __restrict__ C,
    int M, int Nc, int K) {
    __shared__ float As[16][128];
    __shared__ float Bs[16][128];
    const int bm = blockIdx.y * 128, bn = blockIdx.x * 128;
    const int tid = threadIdx.x;
    const int tx = tid & 15, ty = tid >> 4;
    const int alr = tid >> 2, alc = (tid & 3) << 2;   // A/B-T loads
    const int blr = tid >> 5, blc = (tid & 31) << 2;  // B-N loads
    float acc[8][8] = {};

    for (int k0 = 0; k0 < K; k0 += 16) {
        #pragma unroll
        for (int hh = 0; hh < 2; ++hh) {
            float4 v = *(const float4*)&A[(size_t)(bm + alr + hh * 64) * K + k0 + alc];
            As[alc + 0][alr + hh * 64] = v.x;
            As[alc + 1][alr + hh * 64] = v.y;
            As[alc + 2][alr + hh * 64] = v.z;
            As[alc + 3][alr + hh * 64] = v.w;
        }
        if (!TRANSB) {
            #pragma unroll
            for (int hh = 0; hh < 2; ++hh)
                *(float4*)&Bs[blr + hh * 8][blc] =
                    *(const float4*)&B[(size_t)(k0 + blr + hh * 8) * Nc + bn + blc];
        } else {
            #pragma unroll
            for (int hh = 0; hh < 2; ++hh) {
                float4 v = *(const float4*)&B[(size_t)(bn + alr + hh * 64) * K + k0 + alc];
                Bs[alc + 0][alr + hh * 64] = v.x;
                Bs[alc + 1][alr + hh * 64] = v.y;
                Bs[alc + 2][alr + hh * 64] = v.z;
                Bs[alc + 3][alr + hh * 64] = v.w;
            }
        }
        __syncthreads();
        #pragma unroll
        for (int kk = 0; kk < 16; ++kk) {
            float a[8], b[8];
            *(float4*)&a[0] = *(const float4*)&As[kk][ty * 4];
            *(float4*)&a[4] = *(const float4*)&As[kk][64 + ty * 4];
            *(float4*)&b[0] = *(const float4*)&Bs[kk][tx * 4];
            *(float4*)&b[4] = *(const float4*)&Bs[kk][64 + tx * 4];
            #pragma unroll
            for (int i = 0; i < 8; ++i)
                #pragma unroll
                for (int j = 0; j < 8; ++j)
                    acc[i][j] = fmaf(a[i], b[j], acc[i][j]);
        }
        __syncthreads();
    }

    const int rr[2] = {ty * 4, 64 + ty * 4};
    const int cc[2] = {tx * 4, 64 + tx * 4};
    float4 bv[2] = {};
    if (bias) {
        bv[0] = *(const float4*)&bias[bn + cc[0]];
        bv[1] = *(const float4*)&bias[bn + cc[1]];
    }
    #pragma unroll
    for (int ih = 0; ih < 2; ++ih)
        #pragma unroll
        for (int i = 0; i < 4; ++i) {
            int row = bm + rr[ih] + i;
            #pragma unroll
            for (int jh = 0; jh < 2; ++jh) {
                float4 v;
                v.x = acc[ih * 4 + i][jh * 4 + 0];
                v.y = acc[ih * 4 + i][jh * 4 + 1];
                v.z = acc[ih * 4 + i][jh * 4 + 2];
                v.w = acc[ih * 4 + i][jh * 4 + 3];
                if (bias) { v.x += (jh ? bv[1].x : bv[0].x); v.y += (jh ? bv[1].y : bv[0].y);
                            v.z += (jh ? bv[1].z : bv[0].z); v.w += (jh ? bv[1].w : bv[0].w); }
                if (RELU) { v.x = fmaxf(v.x, 0.f); v.y = fmaxf(v.y, 0.f);
                            v.z = fmaxf(v.z, 0.f); v.w = fmaxf(v.w, 0.f); }
                *(float4*)&C[(size_t)row * Nc + bn + cc[jh]] = v;
            }
        }
}

// ---------------- flash attention (fp32) ----------------
// block = (qtile, head), 256 threads, 64-row query tile, stream 64-row K/V tiles.
constexpr int APAD = 68;  // padded row stride (floats), 16B-aligned
constexpr int ATTN_SMEM = (4 * 64 * APAD + 3 * 64) * (int)sizeof(float);

__global__ void __launch_bounds__(256) attn_kernel(const float* __restrict__ qkv,
                                                   float* __restrict__ ctx) {
    extern __shared__ float smem[];
    float* Qs = smem;                 // [d][r]
    float* Ks = Qs + 64 * APAD;       // [d][j]
    float* Vs = Ks + 64 * APAD;       // [j][d]
    float* Ps = Vs + 64 * APAD;       // [j][r]
    float* rm_ = Ps + 64 * APAD;
    float* rl_ = rm_ + 64;
    float* rs_ = rl_ + 64;

    const int qt = blockIdx.x, hh = blockIdx.y;
    const int tid = threadIdx.x;
    const int tx = tid & 15, ty = tid >> 4;
    const int d4 = tx * 4, r4 = ty * 4;

    // load Q (transposed into [d][r])
    #pragma unroll
    for (int i = 0; i < 4; ++i) {
        int r = r4 + i;
        float4 v = *(const float4*)&qkv[(size_t)(qt * 64 + r) * H3 + hh * HD + d4];
        Qs[(d4 + 0) * APAD + r] = v.x;
        Qs[(d4 + 1) * APAD + r] = v.y;
        Qs[(d4 + 2) * APAD + r] = v.z;
        Qs[(d4 + 3) * APAD + r] = v.w;
    }
    if (tid < 64) { rm_[tid] = -1e30f; rl_[tid] = 0.f; }

    float o[4][4] = {};
    for (int kt = 0; kt < Nn / 64; ++kt) {
        __syncthreads();
        // load K (transposed) and V (natural)
        #pragma unroll
        for (int i = 0; i < 4; ++i) {
            int j = r4 + i;
            const float* row = &qkv[(size_t)(kt * 64 + j) * H3 + hh * HD + d4];
            float4 kv = *(const float4*)(row + Hh);
            Ks[(d4 + 0) * APAD + j] = kv.x;
            Ks[(d4 + 1) * APAD + j] = kv.y;
            Ks[(d4 + 2) * APAD + j] = kv.z;
            Ks[(d4 + 3) * APAD + j] = kv.w;
            float4 vv = *(const float4*)(row + 2 * Hh);
            *(float4*)&Vs[j * APAD + d4] = vv;
        }
        __syncthreads();

        // S = (Q K^T) * 1/sqrt(HD), 4x4 per thread
        float s[4][4] = {};
        #pragma unroll 8
        for (int kk = 0; kk < 64; ++kk) {
            float4 qa = *(const float4*)&Qs[kk * APAD + r4];
            float4 kb = *(const float4*)&Ks[kk * APAD + d4];
            float a[4] = {qa.x, qa.y, qa.z, qa.w};
            float b[4] = {kb.x, kb.y, kb.z, kb.w};
            #pragma unroll
            for (int i = 0; i < 4; ++i)
                #pragma unroll
                for (int j = 0; j < 4; ++j)
                    s[i][j] = fmaf(a[i], b[j], s[i][j]);
        }
        // online softmax per row (rows owned by 16-lane group)
        #pragma unroll
        for (int i = 0; i < 4; ++i) {
            int r = r4 + i;
            float mx = -1e30f;
            #pragma unroll
            for (int j = 0; j < 4; ++j) { s[i][j] *= 0.125f; mx = fmaxf(mx, s[i][j]); }
            #pragma unroll
            for (int m = 8; m; m >>= 1) mx = fmaxf(mx, __shfl_xor_sync(0xffffffffu, mx, m));
            float mold = rm_[r];
            float mnew = fmaxf(mold, mx);
            float ls = 0.f;
            #pragma unroll
            for (int j = 0; j < 4; ++j) { float p = __expf(s[i][j] - mnew); s[i][j] = p; ls += p; }
            #pragma unroll
            for (int m = 8; m; m >>= 1) ls += __shfl_xor_sync(0xffffffffu, ls, m);
            if (tx == 0) {
                float sc = __expf(mold - mnew);
                rs_[r] = sc;
                rl_[r] = rl_[r] * sc + ls;
                rm_[r] = mnew;
            }
            #pragma unroll
            for (int j = 0; j < 4; ++j) Ps[(d4 + j) * APAD + r] = s[i][j];
        }
        __syncwarp();  // order rs_ write (tx==0) before reads by the row-group

        // O = O*scale + P V   (thread tile: rows r4.., cols d4..)
        float sc[4];
        #pragma unroll
        for (int i = 0; i < 4; ++i) sc[i] = rs_[r4 + i];
        #pragma unroll
        for (int i = 0; i < 4; ++i)
            #pragma unroll
            for (int j = 0; j < 4; ++j) o[i][j] *= sc[i];
        __syncthreads();  // Ps fully written by all warps before PV
        #pragma unroll 8
        for (int jj = 0; jj < 64; ++jj) {
            float4 pa = *(const float4*)&Ps[jj * APAD + r4];
            float4 vb = *(const float4*)&Vs[jj * APAD + d4];
            float a[4] = {pa.x, pa.y, pa.z, pa.w};
            float b[4] = {vb.x, vb.y, vb.z, vb.w};
            #pragma unroll
            for (int i = 0; i < 4; ++i)
                #pragma unroll
                for (int j = 0; j < 4; ++j)
                    o[i][j] = fmaf(a[i], b[j], o[i][j]);
        }
    }
    __syncthreads();
    #pragma unroll
    for (int i = 0; i < 4; ++i) {
        float inv = 1.0f / rl_[r4 + i];
        int row = qt * 64 + r4 + i;
        float4 v = {o[i][0] * inv, o[i][1] * inv, o[i][2] * inv, o[i][3] * inv};
        *(float4*)&ctx[(size_t)row * Hh + hh * HD + d4] = v;
    }
}

// ---------------- layernorm(residual) ----------------
// out = LN(a + r) * g + b, row width 256; warp per row
__global__ void ln_res_kernel(const float* __restrict__ a, const float* __restrict__ r,
                              const float* __restrict__ g, const float* __restrict__ bb,
                              float* __restrict__ out) {
    int lane = threadIdx.x & 31, w = threadIdx.x >> 5;
    int row = blockIdx.x * 8 + w;
    if (row >= Nn) return;
    size_t base = (size_t)row * Hh;
    float v[8];
    float s = 0.f;
    #pragma unroll
    for (int j = 0; j < 8; ++j) {
        int c = j * 32 + lane;
        v[j] = a[base + c] + r[base + c];
        s += v[j];
    }
    #pragma unroll
    for (int m = 16; m; m >>= 1) s += __shfl_xor_sync(0xffffffffu, s, m);
    float mu = s * (1.0f / Hh);
    float q = 0.f;
    #pragma unroll
    for (int j = 0; j < 8; ++j) { float d = v[j] - mu; q += d * d; }
    #pragma unroll
    for (int m = 16; m; m >>= 1) q += __shfl_xor_sync(0xffffffffu, q, m);
    float rstd = rsqrtf(q * (1.0f / Hh) + 1e-5f);
    #pragma unroll
    for (int j = 0; j < 8; ++j) {
        int c = j * 32 + lane;
        out[base + c] = (v[j] - mu) * rstd * g[c] + bb[c];
    }
}

// ---------------- classifier head: log_softmax(xf @ W_cls + b) ----------------
__global__ void cls_kernel(const float* __restrict__ xf, const float* __restrict__ W,
                           const float* __restrict__ b, float* __restrict__ out) {
    int lane = threadIdx.x & 31, w = threadIdx.x >> 5;
    int row = blockIdx.x * 8 + w;
    if (row >= Nn) return;
    float xv[8];
    #pragma unroll
    for (int j = 0; j < 8; ++j) xv[j] = xf[(size_t)row * Hh + j * 32 + lane];
    float lg[NC];
    #pragma unroll
    for (int c = 0; c < NC; ++c) {
        float p = 0.f;
        #pragma unroll
        for (int j = 0; j < 8; ++j) p += xv[j] * W[(j * 32 + lane) * NC + c];
        #pragma unroll
        for (int m = 16; m; m >>= 1) p += __shfl_xor_sync(0xffffffffu, p, m);
        lg[c] = p + b[c];
    }
    float mx = -1e30f;
    #pragma unroll
    for (int c = 0; c < NC; ++c) mx = fmaxf(mx, lg[c]);
    float se = 0.f;
    #pragma unroll
    for (int c = 0; c < NC; ++c) se += expf(lg[c] - mx);
    float lse = mx + logf(se);
    if (lane < NC) out[(size_t)row * NC + lane] = lg[lane] - lse;
}

// ---------------- decoder second layer: sigmoid(t @ W_d2 + b) ----------------
__global__ void dec2_kernel(const float* __restrict__ t, const float* __restrict__ W,
                            const float* __restrict__ b, float* __restrict__ out) {
    int lane = threadIdx.x & 31, w = threadIdx.x >> 5;
    int row = blockIdx.x * 8 + w;
    if (row >= Nn) return;
    float xv[16];
    #pragma unroll
    for (int j = 0; j < 16; ++j) xv[j] = t[(size_t)row * Hd2 + j * 32 + lane];
    float res[3];
    #pragma unroll
    for (int c = 0; c < 3; ++c) {
        float p = 0.f;
        #pragma unroll
        for (int j = 0; j < 16; ++j) p += xv[j] * W[(j * 32 + lane) * 3 + c];
        #pragma unroll
        for (int m = 16; m; m >>= 1) p += __shfl_xor_sync(0xffffffffu, p, m);
        res[c] = p + b[c];
    }
    if (lane == 0) {
        #pragma unroll
        for (int c = 0; c < 3; ++c)
            out[(size_t)row * 3 + c] = 1.0f / (1.0f + expf(-res[c]));
    }
}

// ---------------- host ----------------
extern "C" void kernel_launch(void* const* d_in, const int* in_sizes, int n_in,
                              void* d_out, int out_size) {
    const float* x          = (const float*)d_in[0];
    const int*   ei         = (const int*)  d_in[1];
    const float* ea         = (const float*)d_in[2];
    const float* W_gcn1     = (const float*)d_in[3];
    const float* b_gcn1     = (const float*)d_in[4];
    const float* W_gcn2     = (const float*)d_in[5];
    const float* b_gcn2     = (const float*)d_in[6];
    const float* in_proj_w  = (const float*)d_in[7];
    const float* in_proj_b  = (const float*)d_in[8];
    const float* out_proj_w = (const float*)d_in[9];
    const float* out_proj_b = (const float*)d_in[10];
    const float* ln1_g      = (const float*)d_in[11];
    const float* ln1_b      = (const float*)d_in[12];
    const float* ffn_w1     = (const float*)d_in[13];
    const float* ffn_b1     = (const float*)d_in[14];
    const float* ffn_w2     = (const float*)d_in[15];
    const float* ffn_b2     = (const float*)d_in[16];
    const float* ln2_g      = (const float*)d_in[17];
    const float* ln2_b      = (const float*)d_in[18];
    const float* W_cls      = (const float*)d_in[19];
    const float* b_cls      = (const float*)d_in[20];
    const float* W_d1       = (const float*)d_in[21];
    const float* b_d1       = (const float*)d_in[22];
    const float* W_d2       = (const float*)d_in[23];
    const float* b_d2       = (const float*)d_in[24];
    float* out = (float*)d_out;

    float* base = nullptr;
    cudaGetSymbolAddress((void**)&base, g_scratch);
    float* deg     = base + OFF_DEG;
    float* dinv    = base + OFF_DINV;
    float* h       = base + OFF_H;
    float* agg     = base + OFF_AGG;
    float* xlocal  = base + OFF_XLOC;
    float* qkv     = base + OFF_QKV;
    float* ctx     = base + OFF_CTX;
    float* attnout = base + OFF_ATTN;
    float* y       = base + OFF_Y;
    float* ffn     = base + OFF_FFN;

    cudaFuncSetAttribute(attn_kernel, cudaFuncAttributeMaxDynamicSharedMemorySize, ATTN_SMEM);

    const int EW = Nn * (Hh / 4);  // elementwise float4 count

    // degree / normalization
    deg_init_kernel<<<Nn / 256, 256>>>(deg);
    deg_scatter_kernel<<<Ee / 256, 256>>>(ei, ea, deg);
    dinv_kernel<<<Nn / 256, 256>>>(deg, dinv);

    // GCN layer 1
    gemm_kernel<false, false><<<dim3(Hh / 128, Nn / 128), 256>>>(x, W_gcn1, nullptr, h, Nn, Hh, Cin);
    selfloop_kernel<<<EW / 256, 256>>>(h, dinv, agg);
    edge_scatter_kernel<<<(Ee * 32) / 256, 256>>>(ei, ea, dinv, h, agg);
    bias_act_kernel<<<EW / 256, 256>>>(agg, b_gcn1, 1);

    // GCN layer 2
    gemm_kernel<false, false><<<dim3(Hh / 128, Nn / 128), 256>>>(agg, W_gcn2, nullptr, h, Nn, Hh, Hh);
    selfloop_kernel<<<EW / 256, 256>>>(h, dinv, xlocal);
    edge_scatter_kernel<<<(Ee * 32) / 256, 256>>>(ei, ea, dinv, h, xlocal);
    bias_act_kernel<<<EW / 256, 256>>>(xlocal, b_gcn2, 0);

    // Transformer: QKV projection (x @ W^T + b)
    gemm_kernel<true, false><<<dim3(H3 / 128, Nn / 128), 256>>>(xlocal, in_proj_w, in_proj_b, qkv, Nn, H3, Hh);

    // flash attention
    attn_kernel<<<dim3(Nn / 64, NH), 256, ATTN_SMEM>>>(qkv, ctx);

    // output projection
    gemm_kernel<true, false><<<dim3(Hh / 128, Nn / 128), 256>>>(ctx, out_proj_w, out_proj_b, attnout, Nn, Hh, Hh);

    // post-norm 1
    ln_res_kernel<<<Nn / 8, 256>>>(xlocal, attnout, ln1_g, ln1_b, y);

    // FFN
    gemm_kernel<false, true><<<dim3(H4 / 128, Nn / 128), 256>>>(y, ffn_w1, ffn_b1, ffn, Nn, H4, Hh);
    gemm_kernel<false, false><<<dim3(Hh / 128, Nn / 128), 256>>>(ffn, ffn_w2, ffn_b2, h, Nn, Hh, H4);

    // post-norm 2 -> x_global (in agg)
    ln_res_kernel<<<Nn / 8, 256>>>(y, h, ln2_g, ln2_b, agg);

    // x_final = x_local + x_global (into ctx)
    add_kernel<<<EW / 256, 256>>>(xlocal, agg, ctx);

    // classifier head -> out[0 : Nn*NC]
    cls_kernel<<<Nn / 8, 256>>>(ctx, W_cls, b_cls, out);

    // decoder
    gemm_kernel<false, true><<<dim3(Hd2 / 128, Nn / 128), 256>>>(ctx, W_d1, b_d1, ffn, Nn, Hd2, Hh);
    dec2_kernel<<<Nn / 8, 256>>>(ffn, W_d2, b_d2, out + (size_t)Nn * NC);
}

// round 4
// speedup vs baseline: 1.9860x; 1.9860x over previous
#include <cuda_runtime.h>
#include <math.h>
#include <stdint.h>

// Problem constants
constexpr int Nn  = 4096;    // nodes
constexpr int Ee  = 131072;  // edges
constexpr int Cin = 128;
constexpr int Hh  = 256;
constexpr int H3  = 768;     // 3H
constexpr int H4  = 1024;    // 4H
constexpr int Hd2 = 512;     // 2H
constexpr int NC  = 16;
constexpr int NH  = 4;
constexpr int HD  = 64;

// ---------------- scratch arena (single device global; no allocation) ----------------
constexpr size_t OFF_DEG    = 0;
constexpr size_t OFF_DINV   = OFF_DEG    + Nn;
constexpr size_t OFF_H      = OFF_DINV   + Nn;
constexpr size_t OFF_AGG    = OFF_H      + (size_t)Nn * Hh;
constexpr size_t OFF_XLOC   = OFF_AGG    + (size_t)Nn * Hh;
constexpr size_t OFF_QKV    = OFF_XLOC   + (size_t)Nn * Hh;
constexpr size_t OFF_CTX    = OFF_QKV    + (size_t)Nn * H3;
constexpr size_t OFF_ATTN   = OFF_CTX    + (size_t)Nn * Hh;
constexpr size_t OFF_Y      = OFF_ATTN   + (size_t)Nn * Hh;
constexpr size_t OFF_FFN    = OFF_Y      + (size_t)Nn * Hh;
constexpr size_t SCRATCH_FLOATS = OFF_FFN + (size_t)Nn * H4;

__device__ float g_scratch[SCRATCH_FLOATS];

// ---------------- tf32 / mma helpers ----------------
__device__ __forceinline__ uint32_t f2tf(float f) {
    uint32_t r; asm("cvt.rna.tf32.f32 %0, %1;" : "=r"(r) : "f"(f)); return r;
}
__device__ __forceinline__ float f2tf_f(float f) { return __uint_as_float(f2tf(f)); }

__device__ __forceinline__ void mma8(float* c,
                                     uint32_t a0, uint32_t a1, uint32_t a2, uint32_t a3,
                                     uint32_t b0, uint32_t b1) {
    asm volatile(
        "mma.sync.aligned.m16n8k8.row.col.f32.tf32.tf32.f32 "
        "{%0,%1,%2,%3}, {%4,%5,%6,%7}, {%8,%9}, {%0,%1,%2,%3};"
        : "+f"(c[0]), "+f"(c[1]), "+f"(c[2]), "+f"(c[3])
        : "r"(a0), "r"(a1), "r"(a2), "r"(a3), "r"(b0), "r"(b1));
}

__device__ __forceinline__ void red_add_v4(float* p, float x, float y, float z, float w) {
    asm volatile("red.global.add.v4.f32 [%0], {%1,%2,%3,%4};"
                 :: "l"(p), "f"(x), "f"(y), "f"(z), "f"(w) : "memory");
}

// ---------------- degree / norm ----------------
__global__ void deg_init_kernel(float* deg) {
    int i = blockIdx.x * blockDim.x + threadIdx.x;
    if (i < Nn) deg[i] = 1.0f;
}
__global__ void deg_scatter_kernel(const int* __restrict__ ei,
                                   const float* __restrict__ ea, float* deg) {
    int e = blockIdx.x * blockDim.x + threadIdx.x;
    if (e < Ee) atomicAdd(&deg[ei[Ee + e]], ea[e]);
}
__global__ void dinv_kernel(const float* __restrict__ deg, float* dinv) {
    int i = blockIdx.x * blockDim.x + threadIdx.x;
    if (i < Nn) dinv[i] = rsqrtf(deg[i]);
}

__global__ void selfloop_kernel(const float* __restrict__ h,
                                const float* __restrict__ dinv,
                                float* __restrict__ out) {
    int i = blockIdx.x * blockDim.x + threadIdx.x;
    if (i >= Nn * (Hh / 4)) return;
    int n = i / (Hh / 4);
    float s = dinv[n]; s *= s;
    float4 v = ((const float4*)h)[i];
    v.x *= s; v.y *= s; v.z *= s; v.w *= s;
    ((float4*)out)[i] = v;
}

__global__ void edge_scatter_kernel(const int* __restrict__ ei,
                                    const float* __restrict__ ea,
                                    const float* __restrict__ dinv,
                                    const float* __restrict__ h,
                                    float* __restrict__ out) {
    int t = blockIdx.x * blockDim.x + threadIdx.x;
    int e = t >> 5, lane = t & 31;
    if (e >= Ee) return;
    int s = ei[e], d = ei[Ee + e];
    float w = dinv[s] * ea[e] * dinv[d];
    const float4* hs = (const float4*)(h + (size_t)s * Hh);
    float* od = out + (size_t)d * Hh;
    #pragma unroll
    for (int q = 0; q < 2; ++q) {
        int idx = lane + q * 32;
        float4 v = hs[idx];
        red_add_v4(od + idx * 4, v.x * w, v.y * w, v.z * w, v.w * w);
    }
}

__global__ void bias_act_kernel(float* __restrict__ x, const float* __restrict__ b, int relu) {
    int i = blockIdx.x * blockDim.x + threadIdx.x;
    if (i >= Nn * (Hh / 4)) return;
    int c = (i & (Hh / 4 - 1)) * 4;
    float4 v = ((float4*)x)[i];
    float4 bv = *(const float4*)&b[c];
    v.x += bv.x; v.y += bv.y; v.z += bv.z; v.w += bv.w;
    if (relu) { v.x = fmaxf(v.x, 0.f); v.y = fmaxf(v.y, 0.f); v.z = fmaxf(v.z, 0.f); v.w = fmaxf(v.w, 0.f); }
    ((float4*)x)[i] = v;
}

__global__ void add_kernel(const float* __restrict__ a, const float* __restrict__ b,
                           float* __restrict__ out) {
    int i = blockIdx.x * blockDim.x + threadIdx.x;
    if (i >= Nn * (Hh / 4)) return;
    float4 va = ((const float4*)a)[i], vb = ((const float4*)b)[i];
    va.x += vb.x; va.y += vb.y; va.z += vb.z; va.w += vb.w;
    ((float4*)out)[i] = va;
}

// ---------------- tensor-core GEMM (3xTF32): C = act(A @ B (+bias)) ----------------
// A [M,K] row-major. TRANSB=false: B [K,N]. TRANSB=true: B [N,K] (C = A@B^T).
// Block 256 thr = 8 warps (4 M x 2 N). Block tile 128x64, K-chunk 32. Warp tile 32x32.
template <bool TRANSB, bool RELU>
__global__ void __launch_bounds__(256) gemm_tc(
    const float* __restrict__ A, const float* __restrict__ B,
    const float* __restrict__ bias, float* __restrict__ C,
    int M, int Nc, int K) {
    __shared__ float As[128][36];
    __shared__ float Bs[64][36];
    const int bm = blockIdx.y * 128, bn = blockIdx.x * 64;
    const int tid = threadIdx.x, lane = tid & 31, wid = tid >> 5;
    const int wm = (wid & 3) * 32, wn = (wid >> 2) * 32;
    const int g = lane >> 2, q = lane & 3;

    float acc[2][4][4] = {};

    for (int k0 = 0; k0 < K; k0 += 32) {
        // load A tile 128x32
        #pragma unroll
        for (int i = 0; i < 4; ++i) {
            int f4 = tid + i * 256;
            int row = f4 >> 3, c4 = (f4 & 7) << 2;
            float4 v = *(const float4*)&A[(size_t)(bm + row) * K + k0 + c4];
            As[row][c4 + 0] = v.x; As[row][c4 + 1] = v.y;
            As[row][c4 + 2] = v.z; As[row][c4 + 3] = v.w;
        }
        // load B tile into Bs[n][k]
        if (TRANSB) {
            #pragma unroll
            for (int i = 0; i < 2; ++i) {
                int f4 = tid + i * 256;
                int row = f4 >> 3, c4 = (f4 & 7) << 2;
                float4 v = *(const float4*)&B[(size_t)(bn + row) * K + k0 + c4];
                Bs[row][c4 + 0] = v.x; Bs[row][c4 + 1] = v.y;
                Bs[row][c4 + 2] = v.z; Bs[row][c4 + 3] = v.w;
            }
        } else {
            #pragma unroll
            for (int i = 0; i < 2; ++i) {
                int f4 = tid + i * 256;
                int kk = f4 >> 4, n4 = (f4 & 15) << 2;
                float4 v = *(const float4*)&B[(size_t)(k0 + kk) * Nc + bn + n4];
                Bs[n4 + 0][kk] = v.x; Bs[n4 + 1][kk] = v.y;
                Bs[n4 + 2][kk] = v.z; Bs[n4 + 3][kk] = v.w;
            }
        }
        __syncthreads();

        #pragma unroll
        for (int ks = 0; ks < 4; ++ks) {
            const int kb = ks * 8;
            uint32_t ah[2][4], al[2][4];
            #pragma unroll
            for (int mt = 0; mt < 2; ++mt) {
                const int r0 = wm + mt * 16 + g;
                float f0 = As[r0][kb + q];
                float f1 = As[r0 + 8][kb + q];
                float f2 = As[r0][kb + q + 4];
                float f3 = As[r0 + 8][kb + q + 4];
                ah[mt][0] = f2tf(f0); al[mt][0] = f2tf(f0 - __uint_as_float(ah[mt][0]));
                ah[mt][1] = f2tf(f1); al[mt][1] = f2tf(f1 - __uint_as_float(ah[mt][1]));
                ah[mt][2] = f2tf(f2); al[mt][2] = f2tf(f2 - __uint_as_float(ah[mt][2]));
                ah[mt][3] = f2tf(f3); al[mt][3] = f2tf(f3 - __uint_as_float(ah[mt][3]));
            }
            #pragma unroll
            for (int nt = 0; nt < 4; ++nt) {
                const int n0 = wn + nt * 8 + g;
                float g0 = Bs[n0][kb + q];
                float g1 = Bs[n0][kb + q + 4];
                uint32_t bh0 = f2tf(g0), bl0 = f2tf(g0 - __uint_as_float(bh0));
                uint32_t bh1 = f2tf(g1), bl1 = f2tf(g1 - __uint_as_float(bh1));
                #pragma unroll
                for (int mt = 0; mt < 2; ++mt) {
                    mma8(acc[mt][nt], ah[mt][0], ah[mt][1], ah[mt][2], ah[mt][3], bh0, bh1);
                    mma8(acc[mt][nt], al[mt][0], al[mt][1], al[mt][2], al[mt][3], bh0, bh1);
                    mma8(acc[mt][nt], ah[mt][0], ah[mt][1], ah[mt][2], ah[mt][3], bl0, bl1);
                }
            }
        }
        __syncthreads();
    }

    // epilogue
    #pragma unroll
    for (int mt = 0; mt < 2; ++mt) {
        const int r0 = bm + wm + mt * 16 + g;
        #pragma unroll
        for (int nt = 0; nt < 4; ++nt) {
            const int cc = bn + wn + nt * 8 + 2 * q;
            float2 v0 = {acc[mt][nt][0], acc[mt][nt][1]};
            float2 v1 = {acc[mt][nt][2], acc[mt][nt][3]};
            if (bias) {
                float2 bb = *(const float2*)&bias[cc];
                v0.x += bb.x; v0.y += bb.y; v1.x += bb.x; v1.y += bb.y;
            }
            if (RELU) {
                v0.x = fmaxf(v0.x, 0.f); v0.y = fmaxf(v0.y, 0.f);
                v1.x = fmaxf(v1.x, 0.f); v1.y = fmaxf(v1.y, 0.f);
            }
            *(float2*)&C[(size_t)r0 * Nc + cc] = v0;
            *(float2*)&C[(size_t)(r0 + 8) * Nc + cc] = v1;
        }
    }
}

// ---------------- flash attention (tf32 tensor cores) ----------------
// block = (qtile 64 rows, head), 128 threads = 4 warps, each warp owns 16 q rows.
constexpr int AP = 68;  // padded smem row stride (floats)
constexpr int ATTN_SMEM = 4 * 64 * AP * (int)sizeof(float);  // Qs, Ks, Vt, Ps

__global__ void __launch_bounds__(128) attn_tc(const float* __restrict__ qkv,
                                               float* __restrict__ ctx) {
    extern __shared__ float smem[];
    float* Qs = smem;              // [r][d]   tf32
    float* Ks = Qs + 64 * AP;      // [j][d]   tf32
    float* Vt = Ks + 64 * AP;      // [d][j]   tf32 (transposed)
    float* Ps = Vt + 64 * AP;      // [r][j]   tf32

    const int qt = blockIdx.x, hh = blockIdx.y;
    const int tid = threadIdx.x, lane = tid & 31, wid = tid >> 5;
    const int wr = wid * 16;            // warp's query-row base
    const int g = lane >> 2, q = lane & 3;

    // load Q tile (64x64), convert to tf32
    #pragma unroll
    for (int it = 0; it < 8; ++it) {
        int idx = tid + it * 128;
        int row = idx >> 4, c4 = (idx & 15) << 2;
        float4 v = *(const float4*)&qkv[(size_t)(qt * 64 + row) * H3 + hh * HD + c4];
        Qs[row * AP + c4 + 0] = f2tf_f(v.x);
        Qs[row * AP + c4 + 1] = f2tf_f(v.y);
        Qs[row * AP + c4 + 2] = f2tf_f(v.z);
        Qs[row * AP + c4 + 3] = f2tf_f(v.w);
    }

    float rm0 = -1e30f, rm1 = -1e30f, rl0 = 0.f, rl1 = 0.f;
    float o[8][4] = {};

    for (int kt = 0; kt < Nn / 64; ++kt) {
        __syncthreads();
        // K tile (64x64) natural [j][d]
        #pragma unroll
        for (int it = 0; it < 8; ++it) {
            int idx = tid + it * 128;
            int row = idx >> 4, c4 = (idx & 15) << 2;
            float4 v = *(const float4*)&qkv[(size_t)(kt * 64 + row) * H3 + Hh + hh * HD + c4];
            Ks[row * AP + c4 + 0] = f2tf_f(v.x);
            Ks[row * AP + c4 + 1] = f2tf_f(v.y);
            Ks[row * AP + c4 + 2] = f2tf_f(v.z);
            Ks[row * AP + c4 + 3] = f2tf_f(v.w);
        }
        // V tile transposed into Vt[d][j]; coalesced gmem reads (lane -> d)
        #pragma unroll
        for (int it = 0; it < 32; ++it) {
            int idx = tid + it * 128;
            int d = idx & 63, j = idx >> 6;
            float v = qkv[(size_t)(kt * 64 + j) * H3 + 2 * Hh + hh * HD + d];
            Vt[d * AP + j] = f2tf_f(v);
        }
        __syncthreads();

        // S = Q K^T (tf32 mma), 8 n-tiles per warp
        float s[8][4] = {};
        #pragma unroll
        for (int ks = 0; ks < 8; ++ks) {
            const int kb = ks * 8;
            uint32_t a0 = __float_as_uint(Qs[(wr + g) * AP + kb + q]);
            uint32_t a1 = __float_as_uint(Qs[(wr + g + 8) * AP + kb + q]);
            uint32_t a2 = __float_as_uint(Qs[(wr + g) * AP + kb + q + 4]);
            uint32_t a3 = __float_as_uint(Qs[(wr + g + 8) * AP + kb + q + 4]);
            #pragma unroll
            for (int nt = 0; nt < 8; ++nt) {
                uint32_t b0 = __float_as_uint(Ks[(nt * 8 + g) * AP + kb + q]);
                uint32_t b1 = __float_as_uint(Ks[(nt * 8 + g) * AP + kb + q + 4]);
                mma8(s[nt], a0, a1, a2, a3, b0, b1);
            }
        }

        // online softmax; thread owns rows (wr+g) via regs 0,1 and (wr+g+8) via regs 2,3
        float mx0 = -1e30f, mx1 = -1e30f;
        #pragma unroll
        for (int nt = 0; nt < 8; ++nt) {
            s[nt][0] *= 0.125f; s[nt][1] *= 0.125f; s[nt][2] *= 0.125f; s[nt][3] *= 0.125f;
            mx0 = fmaxf(mx0, fmaxf(s[nt][0], s[nt][1]));
            mx1 = fmaxf(mx1, fmaxf(s[nt][2], s[nt][3]));
        }
        mx0 = fmaxf(mx0, __shfl_xor_sync(0xffffffffu, mx0, 1));
        mx0 = fmaxf(mx0, __shfl_xor_sync(0xffffffffu, mx0, 2));
        mx1 = fmaxf(mx1, __shfl_xor_sync(0xffffffffu, mx1, 1));
        mx1 = fmaxf(mx1, __shfl_xor_sync(0xffffffffu, mx1, 2));
        float mn0 = fmaxf(rm0, mx0), mn1 = fmaxf(rm1, mx1);
        float l0 = 0.f, l1 = 0.f;
        #pragma unroll
        for (int nt = 0; nt < 8; ++nt) {
            s[nt][0] = __expf(s[nt][0] - mn0); l0 += s[nt][0];
            s[nt][1] = __expf(s[nt][1] - mn0); l0 += s[nt][1];
            s[nt][2] = __expf(s[nt][2] - mn1); l1 += s[nt][2];
            s[nt][3] = __expf(s[nt][3] - mn1); l1 += s[nt][3];
        }
        l0 += __shfl_xor_sync(0xffffffffu, l0, 1);
        l0 += __shfl_xor_sync(0xffffffffu, l0, 2);
        l1 += __shfl_xor_sync(0xffffffffu, l1, 1);
        l1 += __shfl_xor_sync(0xffffffffu, l1, 2);
        float sc0 = __expf(rm0 - mn0), sc1 = __expf(rm1 - mn1);
        rl0 = rl0 * sc0 + l0; rl1 = rl1 * sc1 + l1;
        rm0 = mn0; rm1 = mn1;

        // rescale O accumulators
        #pragma unroll
        for (int dt = 0; dt < 8; ++dt) {
            o[dt][0] *= sc0; o[dt][1] *= sc0; o[dt][2] *= sc1; o[dt][3] *= sc1;
        }

        // write P (tf32) into this warp's private rows of Ps
        #pragma unroll
        for (int nt = 0; nt < 8; ++nt) {
            const int cc = nt * 8 + 2 * q;
            Ps[(wr + g) * AP + cc]     = f2tf_f(s[nt][0]);
            Ps[(wr + g) * AP + cc + 1] = f2tf_f(s[nt][1]);
            Ps[(wr + g + 8) * AP + cc]     = f2tf_f(s[nt][2]);
            Ps[(wr + g + 8) * AP + cc + 1] = f2tf_f(s[nt][3]);
        }
        __syncwarp();

        // O += P V (tf32 mma over key dim)
        #pragma unroll
        for (int ks = 0; ks < 8; ++ks) {
            const int kb = ks * 8;
            uint32_t a0 = __float_as_uint(Ps[(wr + g) * AP + kb + q]);
            uint32_t a1 = __float_as_uint(Ps[(wr + g + 8) * AP + kb + q]);
            uint32_t a2 = __float_as_uint(Ps[(wr + g) * AP + kb + q + 4]);
            uint32_t a3 = __float_as_uint(Ps[(wr + g + 8) * AP + kb + q + 4]);
            #pragma unroll
            for (int dt = 0; dt < 8; ++dt) {
                uint32_t b0 = __float_as_uint(Vt[(dt * 8 + g) * AP + kb + q]);
                uint32_t b1 = __float_as_uint(Vt[(dt * 8 + g) * AP + kb + q + 4]);
                mma8(o[dt], a0, a1, a2, a3, b0, b1);
            }
        }
    }

    // epilogue
    float inv0 = 1.0f / rl0, inv1 = 1.0f / rl1;
    const int r0 = qt * 64 + wr + g;
    #pragma unroll
    for (int dt = 0; dt < 8; ++dt) {
        const int cc = hh * HD + dt * 8 + 2 * q;
        float2 v0 = {o[dt][0] * inv0, o[dt][1] * inv0};
        float2 v1 = {o[dt][2] * inv1, o[dt][3] * inv1};
        *(float2*)&ctx[(size_t)r0 * Hh + cc] = v0;
        *(float2*)&ctx[(size_t)(r0 + 8) * Hh + cc] = v1;
    }
}

// ---------------- layernorm(residual) ----------------
__global__ void ln_res_kernel(const float* __restrict__ a, const float* __restrict__ r,
                              const float* __restrict__ g, const float* __restrict__ bb,
                              float* __restrict__ out) {
    int lane = threadIdx.x & 31, w = threadIdx.x >> 5;
    int row = blockIdx.x * 8 + w;
    if (row >= Nn) return;
    size_t base = (size_t)row * Hh;
    float v[8];
    float s = 0.f;
    #pragma unroll
    for (int j = 0; j < 8; ++j) {
        int c = j * 32 + lane;
        v[j] = a[base + c] + r[base + c];
        s += v[j];
    }
    #pragma unroll
    for (int m = 16; m; m >>= 1) s += __shfl_xor_sync(0xffffffffu, s, m);
    float mu = s * (1.0f / Hh);
    float qv = 0.f;
    #pragma unroll
    for (int j = 0; j < 8; ++j) { float d = v[j] - mu; qv += d * d; }
    #pragma unroll
    for (int m = 16; m; m >>= 1) qv += __shfl_xor_sync(0xffffffffu, qv, m);
    float rstd = rsqrtf(qv * (1.0f / Hh) + 1e-5f);
    #pragma unroll
    for (int j = 0; j < 8; ++j) {
        int c = j * 32 + lane;
        out[base + c] = (v[j] - mu) * rstd * g[c] + bb[c];
    }
}

// ---------------- classifier head ----------------
__global__ void cls_kernel(const float* __restrict__ xf, const float* __restrict__ W,
                           const float* __restrict__ b, float* __restrict__ out) {
    int lane = threadIdx.x & 31, w = threadIdx.x >> 5;
    int row = blockIdx.x * 8 + w;
    if (row >= Nn) return;
    float xv[8];
    #pragma unroll
    for (int j = 0; j < 8; ++j) xv[j] = xf[(size_t)row * Hh + j * 32 + lane];
    float lg[NC];
    #pragma unroll
    for (int c = 0; c < NC; ++c) {
        float p = 0.f;
        #pragma unroll
        for (int j = 0; j < 8; ++j) p += xv[j] * W[(j * 32 + lane) * NC + c];
        #pragma unroll
        for (int m = 16; m; m >>= 1) p += __shfl_xor_sync(0xffffffffu, p, m);
        lg[c] = p + b[c];
    }
    float mx = -1e30f;
    #pragma unroll
    for (int c = 0; c < NC; ++c) mx = fmaxf(mx, lg[c]);
    float se = 0.f;
    #pragma unroll
    for (int c = 0; c < NC; ++c) se += expf(lg[c] - mx);
    float lse = mx + logf(se);
    if (lane < NC) out[(size_t)row * NC + lane] = lg[lane] - lse;
}

// ---------------- decoder second layer ----------------
__global__ void dec2_kernel(const float* __restrict__ t, const float* __restrict__ W,
                            const float* __restrict__ b, float* __restrict__ out) {
    int lane = threadIdx.x & 31, w = threadIdx.x >> 5;
    int row = blockIdx.x * 8 + w;
    if (row >= Nn) return;
    float xv[16];
    #pragma unroll
    for (int j = 0; j < 16; ++j) xv[j] = t[(size_t)row * Hd2 + j * 32 + lane];
    float res[3];
    #pragma unroll
    for (int c = 0; c < 3; ++c) {
        float p = 0.f;
        #pragma unroll
        for (int j = 0; j < 16; ++j) p += xv[j] * W[(j * 32 + lane) * 3 + c];
        #pragma unroll
        for (int m = 16; m; m >>= 1) p += __shfl_xor_sync(0xffffffffu, p, m);
        res[c] = p + b[c];
    }
    if (lane == 0) {
        #pragma unroll
        for (int c = 0; c < 3; ++c)
            out[(size_t)row * 3 + c] = 1.0f / (1.0f + expf(-res[c]));
    }
}

// ---------------- host ----------------
extern "C" void kernel_launch(void* const* d_in, const int* in_sizes, int n_in,
                              void* d_out, int out_size) {
    const float* x          = (const float*)d_in[0];
    const int*   ei         = (const int*)  d_in[1];
    const float* ea         = (const float*)d_in[2];
    const float* W_gcn1     = (const float*)d_in[3];
    const float* b_gcn1     = (const float*)d_in[4];
    const float* W_gcn2     = (const float*)d_in[5];
    const float* b_gcn2     = (const float*)d_in[6];
    const float* in_proj_w  = (const float*)d_in[7];
    const float* in_proj_b  = (const float*)d_in[8];
    const float* out_proj_w = (const float*)d_in[9];
    const float* out_proj_b = (const float*)d_in[10];
    const float* ln1_g      = (const float*)d_in[11];
    const float* ln1_b      = (const float*)d_in[12];
    const float* ffn_w1     = (const float*)d_in[13];
    const float* ffn_b1     = (const float*)d_in[14];
    const float* ffn_w2     = (const float*)d_in[15];
    const float* ffn_b2     = (const float*)d_in[16];
    const float* ln2_g      = (const float*)d_in[17];
    const float* ln2_b      = (const float*)d_in[18];
    const float* W_cls      = (const float*)d_in[19];
    const float* b_cls      = (const float*)d_in[20];
    const float* W_d1       = (const float*)d_in[21];
    const float* b_d1       = (const float*)d_in[22];
    const float* W_d2       = (const float*)d_in[23];
    const float* b_d2       = (const float*)d_in[24];
    float* out = (float*)d_out;

    float* base = nullptr;
    cudaGetSymbolAddress((void**)&base, g_scratch);
    float* deg     = base + OFF_DEG;
    float* dinv    = base + OFF_DINV;
    float* h       = base + OFF_H;
    float* agg     = base + OFF_AGG;
    float* xlocal  = base + OFF_XLOC;
    float* qkv     = base + OFF_QKV;
    float* ctx     = base + OFF_CTX;
    float* attnout = base + OFF_ATTN;
    float* y       = base + OFF_Y;
    float* ffn     = base + OFF_FFN;

    cudaFuncSetAttribute(attn_tc, cudaFuncAttributeMaxDynamicSharedMemorySize, ATTN_SMEM);

    const int EW = Nn * (Hh / 4);

    // degree / normalization
    deg_init_kernel<<<Nn / 256, 256>>>(deg);
    deg_scatter_kernel<<<Ee / 256, 256>>>(ei, ea, deg);
    dinv_kernel<<<Nn / 256, 256>>>(deg, dinv);

    // GCN layer 1
    gemm_tc<false, false><<<dim3(Hh / 64, Nn / 128), 256>>>(x, W_gcn1, nullptr, h, Nn, Hh, Cin);
    selfloop_kernel<<<EW / 256, 256>>>(h, dinv, agg);
    edge_scatter_kernel<<<(Ee * 32) / 256, 256>>>(ei, ea, dinv, h, agg);
    bias_act_kernel<<<EW / 256, 256>>>(agg, b_gcn1, 1);

    // GCN layer 2
    gemm_tc<false, false><<<dim3(Hh / 64, Nn / 128), 256>>>(agg, W_gcn2, nullptr, h, Nn, Hh, Hh);
    selfloop_kernel<<<EW / 256, 256>>>(h, dinv, xlocal);
    edge_scatter_kernel<<<(Ee * 32) / 256, 256>>>(ei, ea, dinv, h, xlocal);
    bias_act_kernel<<<EW / 256, 256>>>(xlocal, b_gcn2, 0);

    // QKV projection (x @ W^T + b)
    gemm_tc<true, false><<<dim3(H3 / 64, Nn / 128), 256>>>(xlocal, in_proj_w, in_proj_b, qkv, Nn, H3, Hh);

    // flash attention (tensor cores)
    attn_tc<<<dim3(Nn / 64, NH), 128, ATTN_SMEM>>>(qkv, ctx);

    // output projection
    gemm_tc<true, false><<<dim3(Hh / 64, Nn / 128), 256>>>(ctx, out_proj_w, out_proj_b, attnout, Nn, Hh, Hh);

    // post-norm 1
    ln_res_kernel<<<Nn / 8, 256>>>(xlocal, attnout, ln1_g, ln1_b, y);

    // FFN
    gemm_tc<false, true><<<dim3(H4 / 64, Nn / 128), 256>>>(y, ffn_w1, ffn_b1, ffn, Nn, H4, Hh);
    gemm_tc<false, false><<<dim3(Hh / 64, Nn / 128), 256>>>(ffn, ffn_w2, ffn_b2, h, Nn, Hh, H4);

    // post-norm 2 -> x_global
    ln_res_kernel<<<Nn / 8, 256>>>(y, h, ln2_g, ln2_b, agg);

    // x_final = x_local + x_global
    add_kernel<<<EW / 256, 256>>>(xlocal, agg, ctx);

    // classifier head
    cls_kernel<<<Nn / 8, 256>>>(ctx, W_cls, b_cls, out);

    // decoder
    gemm_tc<false, true><<<dim3(Hd2 / 64, Nn / 128), 256>>>(ctx, W_d1, b_d1, ffn, Nn, Hd2, Hh);
    dec2_kernel<<<Nn / 8, 256>>>(ffn, W_d2, b_d2, out + (size_t)Nn * NC);
}